// round 1
// baseline (speedup 1.0000x reference)
#include <cuda_runtime.h>

namespace {
constexpr int S  = 8192;
constexpr int D  = 64;
constexpr int W  = 64;
constexpr int TQ = 32;            // queries per CTA
constexpr int KR = TQ + 2 * W;    // 160 key rows per CTA
constexpr int KP = 65;            // padded row pitch (floats) -> conflict-free column reads
constexpr int SP = KR + 1;        // score row pitch
constexpr int NT = 256;
constexpr int SMEM_FLOATS = KR * KP * 2 + TQ * KP + TQ * SP + TQ;
constexpr int SMEM_BYTES  = SMEM_FLOATS * 4;   // 112256 B -> 2 CTAs/SM
}

__global__ __launch_bounds__(NT, 2)
void swa_kernel(const float* __restrict__ Q,
                const float* __restrict__ K,
                const float* __restrict__ V,
                float* __restrict__ O) {
    extern __shared__ float sm[];
    float* Ks = sm;                 // KR x KP
    float* Vs = Ks + KR * KP;       // KR x KP
    float* Qs = Vs + KR * KP;       // TQ x KP
    float* Sc = Qs + TQ * KP;       // TQ x SP
    float* Rw = Sc + TQ * SP;       // TQ (1/sum per query)

    const int tile = blockIdx.x;
    const int b  = tile >> 8;              // S/TQ = 256 tiles per batch
    const int qt = (tile & 255) * TQ;
    const int KB = qt - W;                 // global row index of Ks[0]

    const float* kb = K + (size_t)b * S * D;
    const float* vb = V + (size_t)b * S * D;
    const float* qb = Q + (size_t)b * S * D;

    const int t = threadIdx.x;

    // ---------------- load K/V/Q tiles (vectorized, zero-fill OOB rows) ----
    for (int idx = t; idx < KR * (D / 4); idx += NT) {
        int row = idx >> 4, c = (idx & 15) << 2;
        int kg = KB + row;
        float4 k4 = make_float4(0.f, 0.f, 0.f, 0.f);
        float4 v4 = make_float4(0.f, 0.f, 0.f, 0.f);
        if (kg >= 0 && kg < S) {
            k4 = *(const float4*)(kb + (size_t)kg * D + c);
            v4 = *(const float4*)(vb + (size_t)kg * D + c);
        }
        float* kd = Ks + row * KP + c;
        kd[0] = k4.x; kd[1] = k4.y; kd[2] = k4.z; kd[3] = k4.w;
        float* vd = Vs + row * KP + c;
        vd[0] = v4.x; vd[1] = v4.y; vd[2] = v4.z; vd[3] = v4.w;
    }
    for (int idx = t; idx < TQ * (D / 4); idx += NT) {
        int row = idx >> 4, c = (idx & 15) << 2;
        float4 q4 = *(const float4*)(qb + (size_t)(qt + row) * D + c);
        float* qd = Qs + row * KP + c;
        qd[0] = q4.x; qd[1] = q4.y; qd[2] = q4.z; qd[3] = q4.w;
    }
    __syncthreads();

    const int lane = t & 31;
    const int w    = t >> 5;   // warp 0..7: queries [4w, 4w+4)

    // ---------------- score GEMM: Sc[q][j] = scale * sum_d Qs[q][d]*Ks[j][d]
    {
        float acc[4][5];
        #pragma unroll
        for (int r = 0; r < 4; ++r)
            #pragma unroll
            for (int s = 0; s < 5; ++s) acc[r][s] = 0.f;

        #pragma unroll 8
        for (int d = 0; d < D; ++d) {
            float kk[5];
            #pragma unroll
            for (int s = 0; s < 5; ++s)
                kk[s] = Ks[(lane + 32 * s) * KP + d];   // conflict-free (pad 65)
            #pragma unroll
            for (int r = 0; r < 4; ++r) {
                float qr = Qs[(w * 4 + r) * KP + d];    // warp-broadcast
                #pragma unroll
                for (int s = 0; s < 5; ++s)
                    acc[r][s] = fmaf(qr, kk[s], acc[r][s]);
            }
        }
        const float scale = 0.125f;   // D^-0.5, exact
        #pragma unroll
        for (int r = 0; r < 4; ++r)
            #pragma unroll
            for (int s = 0; s < 5; ++s)
                Sc[(w * 4 + r) * SP + lane + 32 * s] = acc[r][s] * scale;
    }
    __syncthreads();

    // ---------------- masked softmax, 8 threads per query row -------------
    {
        const int row = t >> 3, sub = t & 7;
        // valid local key rows: band [row, row+2W] ∩ global [ -KB, S-1-KB ]
        const int lo = max(row, -KB);
        const int hi = min(row + 2 * W, S - 1 - KB);
        float m = -1e30f;
        for (int j = lo + sub; j <= hi; j += 8)
            m = fmaxf(m, Sc[row * SP + j]);
        m = fmaxf(m, __shfl_xor_sync(0xffffffffu, m, 1));
        m = fmaxf(m, __shfl_xor_sync(0xffffffffu, m, 2));
        m = fmaxf(m, __shfl_xor_sync(0xffffffffu, m, 4));
        float ssum = 0.f;
        for (int j = sub; j < KR; j += 8) {
            float e = 0.f;
            if (j >= lo && j <= hi) {
                e = __expf(Sc[row * SP + j] - m);
                ssum += e;
            }
            Sc[row * SP + j] = e;   // zero outside band -> AV can run full rectangle
        }
        ssum += __shfl_xor_sync(0xffffffffu, ssum, 1);
        ssum += __shfl_xor_sync(0xffffffffu, ssum, 2);
        ssum += __shfl_xor_sync(0xffffffffu, ssum, 4);
        if (sub == 0) Rw[row] = 1.f / ssum;
    }
    __syncthreads();

    // ---------------- AV: O[q][d] = (1/sum) * sum_j P[q][j] * Vs[j][d] ----
    {
        float a0[4] = {0.f, 0.f, 0.f, 0.f};
        float a1[4] = {0.f, 0.f, 0.f, 0.f};
        #pragma unroll 4
        for (int j = 0; j < KR; ++j) {
            float v0 = Vs[j * KP + lane];        // row-broadcast across queries
            float v1 = Vs[j * KP + lane + 32];
            #pragma unroll
            for (int r = 0; r < 4; ++r) {
                float p = Sc[(w * 4 + r) * SP + j];   // warp-broadcast
                a0[r] = fmaf(p, v0, a0[r]);
                a1[r] = fmaf(p, v1, a1[r]);
            }
        }
        #pragma unroll
        for (int r = 0; r < 4; ++r) {
            int qq = w * 4 + r;
            float rinv = Rw[qq];
            size_t o = ((size_t)b * S + qt + qq) * D;
            O[o + lane]      = a0[r] * rinv;
            O[o + lane + 32] = a1[r] * rinv;
        }
    }
}

extern "C" void kernel_launch(void* const* d_in, const int* in_sizes, int n_in,
                              void* d_out, int out_size) {
    const float* q = (const float*)d_in[0];
    const float* k = (const float*)d_in[1];
    const float* v = (const float*)d_in[2];
    float* o = (float*)d_out;
    (void)n_in; (void)out_size;

    cudaFuncSetAttribute(swa_kernel,
                         cudaFuncAttributeMaxDynamicSharedMemorySize, SMEM_BYTES);
    const int B = in_sizes[0] / (S * D);          // 2
    swa_kernel<<<B * (S / TQ), NT, SMEM_BYTES>>>(q, k, v, o);
}

// round 2
// speedup vs baseline: 1.1298x; 1.1298x over previous
#include <cuda_runtime.h>

namespace {
constexpr int S  = 8192;
constexpr int D  = 64;
constexpr int W  = 64;
constexpr int TQ = 32;            // queries per CTA
constexpr int KR = TQ + 2 * W;    // 160 key rows per CTA
constexpr int VP = 68;            // V row pitch (floats): float4-aligned, LDS.64 conflict-free
constexpr int SP = 164;           // score row pitch: float4-aligned for broadcast P reads
constexpr int NT = 256;
// Ks: swizzled [KR][64] + Vs [KR][68] + Qs [TQ][64] + Sc [TQ][164] + Rw[TQ]
constexpr int SMEM_FLOATS = KR * 64 + KR * VP + TQ * 64 + TQ * SP + TQ;
constexpr int SMEM_BYTES  = SMEM_FLOATS * 4;   // 113792 B -> 2 CTAs/SM
}

// ---- packed f32x2 helpers (ptxas never auto-fuses; PTX only) --------------
__device__ __forceinline__ unsigned long long ffma2(unsigned long long acc,
                                                    unsigned long long a,
                                                    unsigned long long b) {
    asm("fma.rn.f32x2 %0, %1, %2, %0;" : "+l"(acc) : "l"(a), "l"(b));
    return acc;
}
__device__ __forceinline__ unsigned long long dup2(float p) {
    unsigned long long u;
    asm("mov.b64 %0, {%1, %1};" : "=l"(u) : "f"(p));
    return u;
}
__device__ __forceinline__ float2 unpack2(unsigned long long u) {
    float2 v;
    asm("mov.b64 {%0, %1}, %2;" : "=f"(v.x), "=f"(v.y) : "l"(u));
    return v;
}

__global__ __launch_bounds__(NT, 2)
void swa_kernel(const float* __restrict__ Q,
                const float* __restrict__ K,
                const float* __restrict__ V,
                float* __restrict__ O) {
    extern __shared__ float sm[];
    float* Ks = sm;                 // KR x 64, float2-XOR-swizzled within row
    float* Vs = Ks + KR * 64;       // KR x VP
    float* Qs = Vs + KR * VP;       // TQ x 64
    float* Sc = Qs + TQ * 64;       // TQ x SP
    float* Rw = Sc + TQ * SP;       // TQ

    const int tile = blockIdx.x;
    const int b  = tile >> 8;
    const int qt = (tile & 255) * TQ;
    const int KB = qt - W;

    const float* kb = K + (size_t)b * S * D;
    const float* vb = V + (size_t)b * S * D;
    const float* qb = Q + (size_t)b * S * D;

    const int t = threadIdx.x;

    // ---------------- load tiles (K swizzled at float2 granularity) -------
    for (int idx = t; idx < KR * (D / 4); idx += NT) {
        int row = idx >> 4, c0 = idx & 15;          // c = 4*c0
        int kg = KB + row;
        float4 k4 = make_float4(0.f, 0.f, 0.f, 0.f);
        float4 v4 = make_float4(0.f, 0.f, 0.f, 0.f);
        if (kg >= 0 && kg < S) {
            k4 = *(const float4*)(kb + (size_t)kg * D + 4 * c0);
            v4 = *(const float4*)(vb + (size_t)kg * D + 4 * c0);
        }
        // K: element (row, d=2*d2+e) lives at Ks[row*64 + 2*(d2 ^ (row&31)) + e]
        int x = row & 31;
        float* krow = Ks + row * 64;
        *(float2*)(krow + 2 * ((2 * c0)     ^ x)) = make_float2(k4.x, k4.y);
        *(float2*)(krow + 2 * ((2 * c0 + 1) ^ x)) = make_float2(k4.z, k4.w);
        *(float4*)(Vs + row * VP + 4 * c0) = v4;
    }
    for (int idx = t; idx < TQ * (D / 4); idx += NT) {
        int row = idx >> 4, c = (idx & 15) << 2;
        *(float4*)(Qs + row * 64 + c) =
            *(const float4*)(qb + (size_t)(qt + row) * D + c);
    }
    __syncthreads();

    const int lane = t & 31;
    const int w    = t >> 5;   // warp w: queries [4w, 4w+4)

    // ---------------- score GEMM (packed over d-pairs) --------------------
    {
        unsigned long long acc[4][5];
        #pragma unroll
        for (int r = 0; r < 4; ++r)
            #pragma unroll
            for (int s = 0; s < 5; ++s) acc[r][s] = 0ull;

        // K pair pointers: row j = lane+32s, pair index (d2 ^ lane) since (j&31)==lane
        const float* krow[5];
        #pragma unroll
        for (int s = 0; s < 5; ++s) krow[s] = Ks + (lane + 32 * s) * 64;

        #pragma unroll 4
        for (int d4 = 0; d4 < 16; ++d4) {          // covers d2 = 2*d4, 2*d4+1
            ulonglong2 q2[4];
            #pragma unroll
            for (int r = 0; r < 4; ++r)            // LDS.128 broadcast
                q2[r] = *(const ulonglong2*)(Qs + (4 * w + r) * 64 + 4 * d4);
            #pragma unroll
            for (int h = 0; h < 2; ++h) {
                int d2 = 2 * d4 + h;
                unsigned long long kk[5];
                #pragma unroll
                for (int s = 0; s < 5; ++s)        // LDS.64 conflict-free (XOR swizzle)
                    kk[s] = *(const unsigned long long*)(krow[s] + 2 * (d2 ^ lane));
                #pragma unroll
                for (int r = 0; r < 4; ++r) {
                    unsigned long long qq = h ? q2[r].y : q2[r].x;
                    #pragma unroll
                    for (int s = 0; s < 5; ++s)
                        acc[r][s] = ffma2(acc[r][s], qq, kk[s]);
                }
            }
        }
        const float scale = 0.125f;
        #pragma unroll
        for (int r = 0; r < 4; ++r)
            #pragma unroll
            for (int s = 0; s < 5; ++s) {
                float2 v = unpack2(acc[r][s]);
                Sc[(4 * w + r) * SP + lane + 32 * s] = (v.x + v.y) * scale;
            }
    }
    __syncthreads();

    // ---------------- masked softmax, 8 threads per query row -------------
    {
        const int row = t >> 3, sub = t & 7;
        const int lo = max(row, -KB);
        const int hi = min(row + 2 * W, S - 1 - KB);
        float m = -1e30f;
        for (int j = lo + sub; j <= hi; j += 8)
            m = fmaxf(m, Sc[row * SP + j]);
        m = fmaxf(m, __shfl_xor_sync(0xffffffffu, m, 1));
        m = fmaxf(m, __shfl_xor_sync(0xffffffffu, m, 2));
        m = fmaxf(m, __shfl_xor_sync(0xffffffffu, m, 4));
        float ssum = 0.f;
        for (int j = sub; j < KR; j += 8) {
            float e = 0.f;
            if (j >= lo && j <= hi) {
                e = __expf(Sc[row * SP + j] - m);
                ssum += e;
            }
            Sc[row * SP + j] = e;
        }
        ssum += __shfl_xor_sync(0xffffffffu, ssum, 1);
        ssum += __shfl_xor_sync(0xffffffffu, ssum, 2);
        ssum += __shfl_xor_sync(0xffffffffu, ssum, 4);
        if (sub == 0) Rw[row] = 1.f / ssum;
    }
    __syncthreads();

    // ---------------- AV (lane owns d = 2*lane, 2*lane+1) -----------------
    {
        unsigned long long a[4] = {0ull, 0ull, 0ull, 0ull};
        const float* vcol = Vs + 2 * lane;
        #pragma unroll 2
        for (int j4 = 0; j4 < KR; j4 += 4) {
            float4 p4[4];
            #pragma unroll
            for (int r = 0; r < 4; ++r)            // LDS.128 broadcast
                p4[r] = *(const float4*)(Sc + (4 * w + r) * SP + j4);
            #pragma unroll
            for (int jj = 0; jj < 4; ++jj) {
                unsigned long long v2 =
                    *(const unsigned long long*)(vcol + (j4 + jj) * VP);
                #pragma unroll
                for (int r = 0; r < 4; ++r) {
                    float p = jj == 0 ? p4[r].x : jj == 1 ? p4[r].y
                            : jj == 2 ? p4[r].z : p4[r].w;
                    a[r] = ffma2(a[r], dup2(p), v2);
                }
            }
        }
        #pragma unroll
        for (int r = 0; r < 4; ++r) {
            int qq = 4 * w + r;
            float rinv = Rw[qq];
            float2 o2 = unpack2(a[r]);
            o2.x *= rinv; o2.y *= rinv;
            *(float2*)(O + ((size_t)b * S + qt + qq) * D + 2 * lane) = o2;
        }
    }
}

extern "C" void kernel_launch(void* const* d_in, const int* in_sizes, int n_in,
                              void* d_out, int out_size) {
    const float* q = (const float*)d_in[0];
    const float* k = (const float*)d_in[1];
    const float* v = (const float*)d_in[2];
    float* o = (float*)d_out;
    (void)n_in; (void)out_size;

    cudaFuncSetAttribute(swa_kernel,
                         cudaFuncAttributeMaxDynamicSharedMemorySize, SMEM_BYTES);
    const int B = in_sizes[0] / (S * D);
    swa_kernel<<<B * (S / TQ), NT, SMEM_BYTES>>>(q, k, v, o);
}